// round 15
// baseline (speedup 1.0000x reference)
#include <cuda_runtime.h>
#include <cstdint>

// out[b,h,w,:] = graph_lstm_output[b, slic[b,h,w]-1, :]
//   graph_lstm_output: [B=4, S=256, C=128] f32   (d_in[0])
//   slic_output:       [B=4, 512, 512] i32       (d_in[1])
//
// R14 fix: R13's illegal access was slic double-offset (global pixel index
// added to batch-local base). Masked to batch-local now. The experiment is
// unchanged: TMA bulk stores (UTMASTG) drain 16 KB contiguous bursts per
// tile from SMEM, vs interleaved per-warp 512 B STG slivers, to test whether
// DRAM burst density is the source of the 24% idle DRAM cycles seen on all
// five STG-path variants (all pinned at 6.0 TB/s / 76%).

static constexpr int TPB        = 256;
static constexpr int TILE_F4    = 1024;                   // 16 KB per tile
static constexpr int TILES      = 4;                      // 64 KB per CTA
static constexpr int CTA_F4     = TILE_F4 * TILES;        // 4096
static constexpr unsigned TOTAL_F4 = 1u << 25;            // 512 MB / 16
static constexpr int NCTA       = TOTAL_F4 / CTA_F4;      // 8192

__device__ __forceinline__ unsigned smem_u32(const void* p)
{
    unsigned a;
    asm("{ .reg .u64 t; cvta.to.shared.u64 t, %1; cvt.u32.u64 %0, t; }"
        : "=r"(a) : "l"(p));
    return a;
}

__global__ __launch_bounds__(TPB)
void convert2image_tma(const float4* __restrict__ src,   // [4*256, 32] f4
                       const int*    __restrict__ slic,  // [4, 2^18]
                       float4*       __restrict__ out)   // [4, 2^18, 32]
{
    __shared__ __align__(128) float4 s_buf[2][TILE_F4];

    const unsigned tid  = threadIdx.x;
    const unsigned base = blockIdx.x * (unsigned)CTA_F4;  // CTA's first f4
                                                          // (global index)

    // All of this CTA's pixels live in one batch (64 KB span, 128 pixels;
    // batch boundaries are 2^23 f4-aligned).
    const unsigned b  = base >> 23;
    const int*    sl  = slic + (b << 18);      // batch-local slic base
    const float4* tb  = src  + (b << 13);      // batch table: 128 KB

    for (int j = 0; j < TILES; j++) {
        const int buf = j & 1;

        // Reuse guard: before overwriting buffer `buf`, the bulk store
        // committed on it 2 iterations ago must have drained.
        if (j >= 2 && tid == 0)
            asm volatile("cp.async.bulk.wait_group 1;" ::: "memory");
        __syncthreads();

        // Gather phase (R8 pattern: 4 independent chains per thread).
        const unsigned tbase = base + (unsigned)j * TILE_F4;  // global f4
        const float4* rowp[4];
        #pragma unroll
        for (int k = 0; k < 4; k++) {
            unsigned g    = tbase + tid + (unsigned)k * TPB;  // global f4
            unsigned lpix = (g >> 5) & ((1u << 18) - 1u);     // batch-local
            int seg = __ldcs(&sl[lpix]) - 1;                  // 0-based
            rowp[k] = tb + (((unsigned)seg) << 5) + (g & 31);
        }
        #pragma unroll
        for (int k = 0; k < 4; k++)
            s_buf[buf][tid + k * TPB] = __ldg(rowp[k]);
        __syncthreads();

        // One 16 KB bulk store per tile (async proxy; full-line bursts).
        if (tid == 0) {
            asm volatile("fence.proxy.async.shared::cta;" ::: "memory");
            asm volatile(
                "cp.async.bulk.global.shared::cta.bulk_group [%0], [%1], %2;"
                :: "l"(out + tbase),
                   "r"(smem_u32(&s_buf[buf][0])),
                   "n"(TILE_F4 * 16)
                : "memory");
            asm volatile("cp.async.bulk.commit_group;" ::: "memory");
        }
    }

    // Drain all outstanding bulk stores before CTA exit.
    if (tid == 0)
        asm volatile("cp.async.bulk.wait_group 0;" ::: "memory");
}

extern "C" void kernel_launch(void* const* d_in, const int* in_sizes, int n_in,
                              void* d_out, int out_size)
{
    const float4* src  = (const float4*)d_in[0];
    const int*    slic = (const int*)d_in[1];
    float4*       out  = (float4*)d_out;

    convert2image_tma<<<NCTA, TPB>>>(src, slic, out);
}

// round 16
// speedup vs baseline: 1.1617x; 1.1617x over previous
#include <cuda_runtime.h>
#include <cstdint>

// out[b,h,w,:] = graph_lstm_output[b, slic[b,h,w]-1, :]
//   graph_lstm_output: [B=4, S=256, C=128] f32   (d_in[0])
//   slic_output:       [B=4, 512, 512] i32       (d_in[1])
//
// R15: TMA stores lose (90.6us, DRAM 68%). Six mechanisms all cap <= 6 TB/s.
// R16 isolates the one variable R9 conflated: L2-prefetch of slic WITHOUT
// switching slic loads to __ldg (that switch, not the prefetch, caused R9's
// L1 thrash). Main kernel = R8 byte-for-byte: __ldcs slic (L2 hit after
// prefetch, L1-bypassing), __ldg batch-local table (L1-hot), __stcs stores.
// Tests: do the 4 MB of DRAM slic reads force read/write turnarounds that
// explain the 24% idle DRAM cycles?

static constexpr unsigned F4_PER_BATCH = 1u << 23;        // 2^18 pix * 32 f4
static constexpr int UNROLL = 4;
static constexpr unsigned CHUNK = F4_PER_BATCH / UNROLL;  // 2^21 f4
static constexpr unsigned THREADS_TOTAL = 1u << 23;       // 2^25 f4 / 4

// ---------------------------------------------------------------------------
// Kernel A: pull slic (4 MB) + table (0.5 MB) into L2. One prefetch per
// 128 B line: 32768 + 4096 = 36864 threads. L2-only — does not touch L1.
// ---------------------------------------------------------------------------
__global__ __launch_bounds__(256)
void l2_prefetch(const int* __restrict__ slic, const float* __restrict__ src)
{
    unsigned t = blockIdx.x * blockDim.x + threadIdx.x;
    if (t < 32768u) {
        const char* p = reinterpret_cast<const char*>(slic) + (size_t)t * 128;
        asm volatile("prefetch.global.L2 [%0];" :: "l"(p));
    } else if (t < 36864u) {
        unsigned u = t - 32768u;
        const char* p = reinterpret_cast<const char*>(src) + (size_t)u * 128;
        asm volatile("prefetch.global.L2 [%0];" :: "l"(p));
    }
}

// ---------------------------------------------------------------------------
// Kernel B: R8 verbatim (best known: 80.2us standalone).
// ---------------------------------------------------------------------------
__global__ __launch_bounds__(256)
void convert2image_l1(const float4* __restrict__ src,   // [4*256, 32] float4
                      const int*    __restrict__ slic,  // [4, 2^18]
                      float4*       __restrict__ out)   // [4, 2^18, 32]
{
    const unsigned t = blockIdx.x * blockDim.x + threadIdx.x;  // [0, 2^23)

    const unsigned b    = t >> 21;             // batch: 2^21 threads per batch
    const unsigned loc  = t & (CHUNK - 1u);    // local f4 base within batch
    const unsigned lane = loc & 31;

    const int*    sl = slic + (b << 18);
    const float4* tb = src  + (b << 13);       // this batch's 128 KB table
    float4*       ob = out  + (b << 23);

    // Phase 1: 4 independent slic loads. __ldcs: L1-bypassing (table owns
    // L1), evict-first in L2 — hits L2 thanks to the prefetch kernel.
    const float4* rowp[UNROLL];
    #pragma unroll
    for (int i = 0; i < UNROLL; i++) {
        unsigned pix = (loc + (unsigned)i * CHUNK) >> 5;
        int seg = __ldcs(&sl[pix]) - 1;        // 0-based segment
        rowp[i] = tb + (((unsigned)seg) << 5); // seg * 32 float4
    }

    // Phase 2: 4 independent gathers from the batch-local L1-hot table.
    float4 v[UNROLL];
    #pragma unroll
    for (int i = 0; i < UNROLL; i++)
        v[i] = __ldg(&rowp[i][lane]);

    // Phase 3: 4 coalesced streaming stores (write-once, evict-first).
    #pragma unroll
    for (int i = 0; i < UNROLL; i++)
        __stcs(&ob[loc + (unsigned)i * CHUNK], v[i]);
}

extern "C" void kernel_launch(void* const* d_in, const int* in_sizes, int n_in,
                              void* d_out, int out_size)
{
    const float4* src  = (const float4*)d_in[0];
    const int*    slic = (const int*)d_in[1];
    float4*       out  = (float4*)d_out;

    l2_prefetch<<<144, 256>>>(slic, (const float*)src);

    const int threads = 256;
    const int blocks  = THREADS_TOTAL / threads;   // 32768
    convert2image_l1<<<blocks, threads>>>(src, slic, out);
}